// round 3
// baseline (speedup 1.0000x reference)
#include <cuda_runtime.h>

#define NTH 256
#define ITEMS 2
#define MAXBLK 4096

__device__ double g_part[11 * MAXBLK];
__device__ int    g_arrive;   // monotone across graph replays
__device__ int    g_flag;     // monotone: (epoch+1)*16 + K

__device__ __forceinline__ float frcp(float a) {
    float r; asm("rcp.approx.f32 %0, %1;" : "=f"(r) : "f"(a)); return r;
}

__device__ __forceinline__ float objf(float x1, float x2, float y1, float y2, float y3) {
    float o = 0.f;
#define TERM(xx, yy) { float a_ = (xx) + (yy); o = fmaf(a_, a_, o); \
                       float m_ = (xx) * (yy); o = fmaf(m_, m_, o); }
    TERM(x1, y1) TERM(x2, y1)
    TERM(x1, y2) TERM(x2, y2)
    TERM(x1, y3) TERM(x2, y3)
#undef TERM
    return o;
}

// One Gauss-Newton step via 2x2 Schur complement of the arrow-structured J^T J.
__device__ __forceinline__ void gn_step(float& x1, float& x2,
                                        float& y1, float& y2, float& y3) {
    float S1 = y1 + y2 + y3;
    float S2 = fmaf(y1, y1, fmaf(y2, y2, y3 * y3));
    float Q  = fmaf(x1, x1, x2 * x2);
    float P1 = x1 + x2;
    float A  = 3.0f + S2;
    float Bv = 2.0f + Q;

    float c11 = fmaf(x1, y1, 1.f), c12 = fmaf(x1, y2, 1.f), c13 = fmaf(x1, y3, 1.f);
    float c21 = fmaf(x2, y1, 1.f), c22 = fmaf(x2, y2, 1.f), c23 = fmaf(x2, y3, 1.f);

    float gx1 = fmaf(x1, S2, fmaf(3.f, x1, S1));
    float gx2 = fmaf(x2, S2, fmaf(3.f, x2, S1));
    float gy1 = fmaf(Bv, y1, P1);
    float gy2 = fmaf(Bv, y2, P1);
    float gy3 = fmaf(Bv, y3, P1);

    float invB = frcp(Bv);   // Bv >= 2, always safe

    float cc11 = fmaf(c11, c11, fmaf(c12, c12, c13 * c13));
    float cc12 = fmaf(c11, c21, fmaf(c12, c22, c13 * c23));
    float cc22 = fmaf(c21, c21, fmaf(c22, c22, c23 * c23));

    float s11 = fmaf(-cc11, invB, A);
    float s12 = -cc12 * invB;
    float s22 = fmaf(-cc22, invB, A);

    float r1 = fmaf(-invB, fmaf(c11, gy1, fmaf(c12, gy2, c13 * gy3)), gx1);
    float r2 = fmaf(-invB, fmaf(c21, gy1, fmaf(c22, gy2, c23 * gy3)), gx2);

    float det  = fmaf(s11, s22, -(s12 * s12));
    float invd = frcp(det);

    float ux1 = fmaf(s22, r1, -(s12 * r2)) * invd;
    float ux2 = fmaf(s11, r2, -(s12 * r1)) * invd;

    float uy1 = (gy1 - fmaf(c11, ux1, c21 * ux2)) * invB;
    float uy2 = (gy2 - fmaf(c12, ux1, c22 * ux2)) * invB;
    float uy3 = (gy3 - fmaf(c13, ux1, c23 * ux2)) * invB;

    x1 -= ux1; x2 -= ux2;
    y1 -= uy1; y2 -= uy2; y3 -= uy3;
}

// Fused kernel. Single wave guaranteed: <=64 regs (launch_bounds min 4 blocks/SM)
// -> 4*148 = 592 resident blocks >= nblk (512). Software grid barrier is safe.
__global__ void __launch_bounds__(NTH, 4)
k_all(const float* __restrict__ xin, const float* __restrict__ yin,
      float* __restrict__ out, int B, int nblk) {
    int tid  = threadIdx.x;
    int base = blockIdx.x * (NTH * ITEMS) + tid;

    float X1[ITEMS], X2[ITEMS], Y1[ITEMS], Y2[ITEMS], Y3[ITEMS];
    bool  valid[ITEMS];
#pragma unroll
    for (int i = 0; i < ITEMS; i++) {
        int b = base + i * NTH;
        valid[i] = (b < B);
        if (valid[i]) {
            float2 xv = *reinterpret_cast<const float2*>(xin + 2 * b);
            X1[i] = xv.x; X2[i] = xv.y;
            Y1[i] = yin[3 * b]; Y2[i] = yin[3 * b + 1]; Y3[i] = yin[3 * b + 2];
        } else {
            X1[i] = 1.f; X2[i] = 0.f; Y1[i] = 1.f; Y2[i] = 0.f; Y3[i] = 0.f;
        }
    }

    float o[11];
#pragma unroll
    for (int t = 0; t < 10; t++) {
        float acc = 0.f;
#pragma unroll
        for (int i = 0; i < ITEMS; i++)
            acc += valid[i] ? objf(X1[i], X2[i], Y1[i], Y2[i], Y3[i]) : 0.f;
        o[t] = acc;
#pragma unroll
        for (int i = 0; i < ITEMS; i++)
            gn_step(X1[i], X2[i], Y1[i], Y2[i], Y3[i]);
    }
    {
        float acc = 0.f;
#pragma unroll
        for (int i = 0; i < ITEMS; i++)
            acc += valid[i] ? objf(X1[i], X2[i], Y1[i], Y2[i], Y3[i]) : 0.f;
        o[10] = acc;
    }

    // s_10 -> d_out optimistically (overwritten below only if K < 10)
#pragma unroll
    for (int i = 0; i < ITEMS; i++) {
        int b = base + i * NTH;
        if (valid[i]) {
            out[2 * b]     = X1[i];
            out[2 * b + 1] = X2[i];
            out[2 * B + 3 * b]     = Y1[i];
            out[2 * B + 3 * b + 1] = Y2[i];
            out[2 * B + 3 * b + 2] = Y3[i];
        }
    }

    // block reduction of objective partials -> g_part
    int lane = tid & 31;
    int wid  = tid >> 5;
    __shared__ float sm[(NTH / 32)][11];
#pragma unroll
    for (int t = 0; t < 11; t++) {
        float v = o[t];
#pragma unroll
        for (int off = 16; off > 0; off >>= 1)
            v += __shfl_down_sync(0xffffffffu, v, off);
        if (lane == 0) sm[wid][t] = v;
    }
    __syncthreads();
    if (wid == 0) {
#pragma unroll
        for (int t = 0; t < 11; t++) {
            float w = (lane < (NTH / 32)) ? sm[lane][t] : 0.f;
#pragma unroll
            for (int off = 4; off > 0; off >>= 1)
                w += __shfl_down_sync(0xffffffffu, w, off);
            if (lane == 0) g_part[t * MAXBLK + blockIdx.x] = (double)w;
        }
    }

    // ---- grid barrier: arrival ----
    __threadfence();
    __shared__ int s_epoch, s_is_last, s_K;
    if (tid == 0) {
        int old = atomicAdd(&g_arrive, 1);
        s_epoch  = old / nblk;            // same value for every block this replay
        s_is_last = ((old % nblk) == (nblk - 1));
    }
    __syncthreads();
    int epoch = s_epoch;

    // ---- last block decides K ----
    if (s_is_last) {
        __shared__ double red[NTH];
        __shared__ double osum[11];
        for (int t = 0; t < 11; t++) {
            double s = 0.0;
            for (int i = tid; i < nblk; i += NTH) s += g_part[t * MAXBLK + i];
            red[tid] = s;
            __syncthreads();
            for (int off = NTH / 2; off > 0; off >>= 1) {
                if (tid < off) red[tid] += red[tid + off];
                __syncthreads();
            }
            if (tid == 0) osum[t] = red[0];
            __syncthreads();
        }
        if (tid == 0) {
            double obj = osum[0];
            int K = 0;
            for (int t = 1; t <= 10; t++) {
                if (osum[t] < obj) { obj = osum[t]; K = t; }
                else break;   // a reject freezes the state forever (reg is a fp32 no-op)
            }
            __threadfence();
            atomicExch(&g_flag, (epoch + 1) * 16 + K);   // monotone publish
        }
    }

    // ---- all blocks wait for the decision ----
    int target = (epoch + 1) * 16;
    if (tid == 0) {
        int f;
        while ((f = *(volatile int*)&g_flag) < target) { }
        s_K = f - target;
    }
    __syncthreads();
    int K = s_K;

    // ---- fixup (only if some iteration rejected; cold path) ----
    if (K != 10) {
#pragma unroll
        for (int i = 0; i < ITEMS; i++) {
            int b = base + i * NTH;
            if (!valid[i]) continue;
            float2 xv = *reinterpret_cast<const float2*>(xin + 2 * b);
            float x1 = xv.x, x2 = xv.y;
            float y1 = yin[3 * b], y2 = yin[3 * b + 1], y3 = yin[3 * b + 2];
            for (int t = 0; t < K; t++) gn_step(x1, x2, y1, y2, y3);
            out[2 * b]     = x1;
            out[2 * b + 1] = x2;
            out[2 * B + 3 * b]     = y1;
            out[2 * B + 3 * b + 1] = y2;
            out[2 * B + 3 * b + 2] = y3;
        }
    }
}

extern "C" void kernel_launch(void* const* d_in, const int* in_sizes, int n_in,
                              void* d_out, int out_size) {
    const float* x = (const float*)d_in[0];   // (B,1,2) float32
    const float* y = (const float*)d_in[1];   // (B,3,1) float32
    int B = in_sizes[0] / 2;
    int nblk = (B + NTH * ITEMS - 1) / (NTH * ITEMS);   // 512 for B=262144

    k_all<<<nblk, NTH>>>(x, y, (float*)d_out, B, nblk);
}

// round 4
// speedup vs baseline: 1.0667x; 1.0667x over previous
#include <cuda_runtime.h>

#define NTH 256
#define ITEMS 2
#define MAXBLK 4096

__device__ double g_part[11 * MAXBLK];
__device__ int    g_arrive;   // monotone across graph replays
__device__ int    g_flag;     // monotone: (epoch+1)*16 + K ; K = g_flag & 15

__device__ __forceinline__ float frcp(float a) {
    float r; asm("rcp.approx.f32 %0, %1;" : "=f"(r) : "f"(a)); return r;
}

// obj = sum (x_j+y_i)^2 + (x_j*y_i)^2 over 3x2 = 3Q + 2*P1*S1 + 2*S2 + Q*S2
__device__ __forceinline__ float obj_from(float Q, float S2, float P1, float S1) {
    return fmaf(Q, S2, fmaf(2.f, fmaf(P1, S1, S2), 3.f * Q));
}

// One Gauss-Newton step via 2x2 Schur complement of the arrow-structured J^T J.
// Also returns the objective at the *input* state (shares S1,S2,Q,P1).
__device__ __forceinline__ float gn_step(float& x1, float& x2,
                                         float& y1, float& y2, float& y3) {
    float S1 = y1 + y2 + y3;
    float S2 = fmaf(y1, y1, fmaf(y2, y2, y3 * y3));
    float Q  = fmaf(x1, x1, x2 * x2);
    float P1 = x1 + x2;
    float obj = obj_from(Q, S2, P1, S1);

    float A  = 3.0f + S2;
    float Bv = 2.0f + Q;

    float c11 = fmaf(x1, y1, 1.f), c12 = fmaf(x1, y2, 1.f), c13 = fmaf(x1, y3, 1.f);
    float c21 = fmaf(x2, y1, 1.f), c22 = fmaf(x2, y2, 1.f), c23 = fmaf(x2, y3, 1.f);

    float gx1 = fmaf(x1, S2, fmaf(3.f, x1, S1));
    float gx2 = fmaf(x2, S2, fmaf(3.f, x2, S1));
    float gy1 = fmaf(Bv, y1, P1);
    float gy2 = fmaf(Bv, y2, P1);
    float gy3 = fmaf(Bv, y3, P1);

    float invB = frcp(Bv);   // Bv >= 2, always safe

    float cc11 = fmaf(c11, c11, fmaf(c12, c12, c13 * c13));
    float cc12 = fmaf(c11, c21, fmaf(c12, c22, c13 * c23));
    float cc22 = fmaf(c21, c21, fmaf(c22, c22, c23 * c23));

    float s11 = fmaf(-cc11, invB, A);
    float s12 = -cc12 * invB;
    float s22 = fmaf(-cc22, invB, A);

    float r1 = fmaf(-invB, fmaf(c11, gy1, fmaf(c12, gy2, c13 * gy3)), gx1);
    float r2 = fmaf(-invB, fmaf(c21, gy1, fmaf(c22, gy2, c23 * gy3)), gx2);

    float det  = fmaf(s11, s22, -(s12 * s12));
    float invd = frcp(det);

    float ux1 = fmaf(s22, r1, -(s12 * r2)) * invd;
    float ux2 = fmaf(s11, r2, -(s12 * r1)) * invd;

    float uy1 = (gy1 - fmaf(c11, ux1, c21 * ux2)) * invB;
    float uy2 = (gy2 - fmaf(c12, ux1, c22 * ux2)) * invB;
    float uy3 = (gy3 - fmaf(c13, ux1, c23 * ux2)) * invB;

    x1 -= ux1; x2 -= ux2;
    y1 -= uy1; y2 -= uy2; y3 -= uy3;
    return obj;
}

__device__ __forceinline__ float obj_of(float x1, float x2,
                                        float y1, float y2, float y3) {
    float S1 = y1 + y2 + y3;
    float S2 = fmaf(y1, y1, fmaf(y2, y2, y3 * y3));
    float Q  = fmaf(x1, x1, x2 * x2);
    float P1 = x1 + x2;
    return obj_from(Q, S2, P1, S1);
}

// K1: compute trajectories, write s_10 optimistically, emit partials, exit.
// Last-arriving block alone computes K and publishes it. NO spinning.
__global__ void __launch_bounds__(NTH, 4)
k_main(const float* __restrict__ xin, const float* __restrict__ yin,
       float* __restrict__ out, int B, int nblk) {
    int tid  = threadIdx.x;
    int base = blockIdx.x * (NTH * ITEMS) + tid;

    float X1[ITEMS], X2[ITEMS], Y1[ITEMS], Y2[ITEMS], Y3[ITEMS];
    bool  valid[ITEMS];
#pragma unroll
    for (int i = 0; i < ITEMS; i++) {
        int b = base + i * NTH;
        valid[i] = (b < B);
        if (valid[i]) {
            float2 xv = *reinterpret_cast<const float2*>(xin + 2 * b);
            X1[i] = xv.x; X2[i] = xv.y;
            Y1[i] = yin[3 * b]; Y2[i] = yin[3 * b + 1]; Y3[i] = yin[3 * b + 2];
        } else {
            X1[i] = 1.f; X2[i] = 0.f; Y1[i] = 1.f; Y2[i] = 0.f; Y3[i] = 0.f;
        }
    }

    float o[11];
#pragma unroll
    for (int t = 0; t < 10; t++) {
        float acc = 0.f;
#pragma unroll
        for (int i = 0; i < ITEMS; i++) {
            float ov = gn_step(X1[i], X2[i], Y1[i], Y2[i], Y3[i]);
            acc += valid[i] ? ov : 0.f;
        }
        o[t] = acc;
    }
    {
        float acc = 0.f;
#pragma unroll
        for (int i = 0; i < ITEMS; i++)
            acc += valid[i] ? obj_of(X1[i], X2[i], Y1[i], Y2[i], Y3[i]) : 0.f;
        o[10] = acc;
    }

    // s_10 -> d_out optimistically (k2 overwrites only if K < 10)
#pragma unroll
    for (int i = 0; i < ITEMS; i++) {
        int b = base + i * NTH;
        if (valid[i]) {
            out[2 * b]     = X1[i];
            out[2 * b + 1] = X2[i];
            out[2 * B + 3 * b]     = Y1[i];
            out[2 * B + 3 * b + 1] = Y2[i];
            out[2 * B + 3 * b + 2] = Y3[i];
        }
    }

    // block reduction of objective partials -> g_part
    int lane = tid & 31;
    int wid  = tid >> 5;
    __shared__ float sm[(NTH / 32)][11];
#pragma unroll
    for (int t = 0; t < 11; t++) {
        float v = o[t];
#pragma unroll
        for (int off = 16; off > 0; off >>= 1)
            v += __shfl_down_sync(0xffffffffu, v, off);
        if (lane == 0) sm[wid][t] = v;
    }
    __syncthreads();
    if (wid == 0) {
#pragma unroll
        for (int t = 0; t < 11; t++) {
            float w = (lane < (NTH / 32)) ? sm[lane][t] : 0.f;
#pragma unroll
            for (int off = 4; off > 0; off >>= 1)
                w += __shfl_down_sync(0xffffffffu, w, off);
            if (lane == 0) g_part[t * MAXBLK + blockIdx.x] = (double)w;
        }
    }

    // arrival; only the last block stays to decide, everyone else exits now
    __threadfence();
    __shared__ int s_epoch, s_is_last;
    if (tid == 0) {
        int old = atomicAdd(&g_arrive, 1);
        s_epoch   = old / nblk;
        s_is_last = ((old % nblk) == (nblk - 1));
    }
    __syncthreads();
    if (!s_is_last) return;

    // ---- last block: reduce + accept-prefix scan, publish K ----
    __shared__ double red[NTH];
    __shared__ double osum[11];
    for (int t = 0; t < 11; t++) {
        double s = 0.0;
        for (int i = tid; i < nblk; i += NTH) s += g_part[t * MAXBLK + i];
        red[tid] = s;
        __syncthreads();
        for (int off = NTH / 2; off > 0; off >>= 1) {
            if (tid < off) red[tid] += red[tid + off];
            __syncthreads();
        }
        if (tid == 0) osum[t] = red[0];
        __syncthreads();
    }
    if (tid == 0) {
        double obj = osum[0];
        int K = 0;
        for (int t = 1; t <= 10; t++) {
            if (osum[t] < obj) { obj = osum[t]; K = t; }
            else break;   // a reject freezes the state forever (reg is a fp32 no-op)
        }
        atomicExch(&g_flag, (s_epoch + 1) * 16 + K);   // monotone publish
    }
}

// K2 (safety net): ordered after k_main by the stream edge. Early-exits when
// K == 10 (the common/observed case); otherwise recomputes the K-step state.
__global__ void __launch_bounds__(NTH)
k_fix(const float* __restrict__ xin, const float* __restrict__ yin,
      float* __restrict__ out, int B) {
    int K = g_flag & 15;
    if (K == 10) return;
    int b = blockIdx.x * NTH + threadIdx.x;
    if (b >= B) return;
    float2 xv = *reinterpret_cast<const float2*>(xin + 2 * b);
    float x1 = xv.x, x2 = xv.y;
    float y1 = yin[3 * b], y2 = yin[3 * b + 1], y3 = yin[3 * b + 2];
    for (int t = 0; t < K; t++) gn_step(x1, x2, y1, y2, y3);
    out[2 * b]     = x1;
    out[2 * b + 1] = x2;
    out[2 * B + 3 * b]     = y1;
    out[2 * B + 3 * b + 1] = y2;
    out[2 * B + 3 * b + 2] = y3;
}

extern "C" void kernel_launch(void* const* d_in, const int* in_sizes, int n_in,
                              void* d_out, int out_size) {
    const float* x = (const float*)d_in[0];   // (B,1,2) float32
    const float* y = (const float*)d_in[1];   // (B,3,1) float32
    int B = in_sizes[0] / 2;
    int nblk1 = (B + NTH * ITEMS - 1) / (NTH * ITEMS);   // 512 for B=262144
    int nblk2 = (B + NTH - 1) / NTH;

    k_main<<<nblk1, NTH>>>(x, y, (float*)d_out, B, nblk1);
    k_fix<<<nblk2, NTH>>>(x, y, (float*)d_out, B);
}

// round 5
// speedup vs baseline: 1.1353x; 1.0643x over previous
#include <cuda_runtime.h>

#define NTH 256
#define ITEMS 2
#define MAXBLK 4096

__device__ double g_part[11 * MAXBLK];
__device__ int    g_arrive;   // monotone across graph replays
__device__ int    g_flag;     // monotone: (epoch+1)*16 + K ; K = g_flag & 15

__device__ __forceinline__ float frcp(float a) {
    float r; asm("rcp.approx.f32 %0, %1;" : "=f"(r) : "f"(a)); return r;
}

// obj = sum (x_j+y_i)^2 + (x_j*y_i)^2 = 3Q + 2*P1*S1 + 2*S2 + Q*S2
__device__ __forceinline__ float obj_from(float Q, float S2, float P1, float S1) {
    return fmaf(Q, S2, fmaf(2.f, fmaf(P1, S1, S2), 3.f * Q));
}

// Slim Gauss-Newton step using the rank-2 structure C = E + x y^T:
//   CC^T_jk = 3 + S1(x_j+x_k) + S2 x_j x_k
//   rhs_j   = 3 x_j - t*P1*(3 + S1 x_j)          (t = 1/Bv, exact cancellation)
//   y_new_i = t*(xu*y_i + Su - P1)               (xu = x.u, Su = ux1+ux2, old x)
// Returns the objective at the INPUT state.
__device__ __forceinline__ float gn_step(float& x1, float& x2,
                                         float& y1, float& y2, float& y3) {
    float S1 = y1 + y2 + y3;
    float S2 = fmaf(y1, y1, fmaf(y2, y2, y3 * y3));
    float Q  = fmaf(x1, x1, x2 * x2);
    float P1 = x1 + x2;
    float obj = obj_from(Q, S2, P1, S1);

    float A  = 3.0f + S2;
    float Bv = 2.0f + Q;
    float t  = frcp(Bv);                 // Bv >= 2, safe

    float q1 = fmaf(S1, x1, 3.f);
    float q2 = fmaf(S1, x2, 3.f);
    float a1 = fmaf(S2, x1, S1);
    float a2 = fmaf(S2, x2, S1);

    float cc11 = fmaf(a1, x1, q1);
    float cc12 = fmaf(a1, x2, q1);
    float cc22 = fmaf(a2, x2, q2);

    float s11 = fmaf(-t, cc11, A);
    float s12 = -t * cc12;
    float s22 = fmaf(-t, cc22, A);

    float tP1 = t * P1;
    float r1 = fmaf(-tP1, q1, 3.f * x1);
    float r2 = fmaf(-tP1, q2, 3.f * x2);

    float det  = fmaf(s11, s22, -(s12 * s12));
    float invd = frcp(det);

    float ux1 = fmaf(s22, r1, -(s12 * r2)) * invd;
    float ux2 = fmaf(s11, r2, -(s12 * r1)) * invd;

    float Su = ux1 + ux2;
    float xu = fmaf(x1, ux1, x2 * ux2);  // uses OLD x
    x1 -= ux1; x2 -= ux2;

    float c = Su - P1;
    y1 = t * fmaf(xu, y1, c);
    y2 = t * fmaf(xu, y2, c);
    y3 = t * fmaf(xu, y3, c);
    return obj;
}

__device__ __forceinline__ float obj_of(float x1, float x2,
                                        float y1, float y2, float y3) {
    float S1 = y1 + y2 + y3;
    float S2 = fmaf(y1, y1, fmaf(y2, y2, y3 * y3));
    float Q  = fmaf(x1, x1, x2 * x2);
    float P1 = x1 + x2;
    return obj_from(Q, S2, P1, S1);
}

// K1: compute trajectories, write s_10 optimistically, emit partials, exit.
// Last-arriving block alone computes K and publishes it. NO spinning.
__global__ void __launch_bounds__(NTH, 4)
k_main(const float* __restrict__ xin, const float* __restrict__ yin,
       float* __restrict__ out, int B, int nblk) {
    int tid  = threadIdx.x;
    int base = blockIdx.x * (NTH * ITEMS) + tid;

    float X1[ITEMS], X2[ITEMS], Y1[ITEMS], Y2[ITEMS], Y3[ITEMS];
    bool  valid[ITEMS];
#pragma unroll
    for (int i = 0; i < ITEMS; i++) {
        int b = base + i * NTH;
        valid[i] = (b < B);
        if (valid[i]) {
            float2 xv = *reinterpret_cast<const float2*>(xin + 2 * b);
            X1[i] = xv.x; X2[i] = xv.y;
            Y1[i] = yin[3 * b]; Y2[i] = yin[3 * b + 1]; Y3[i] = yin[3 * b + 2];
        } else {
            X1[i] = 1.f; X2[i] = 0.f; Y1[i] = 1.f; Y2[i] = 0.f; Y3[i] = 0.f;
        }
    }

    float o[11];
#pragma unroll
    for (int t = 0; t < 10; t++) {
        float acc = 0.f;
#pragma unroll
        for (int i = 0; i < ITEMS; i++) {
            float ov = gn_step(X1[i], X2[i], Y1[i], Y2[i], Y3[i]);
            acc += valid[i] ? ov : 0.f;
        }
        o[t] = acc;
    }
    {
        float acc = 0.f;
#pragma unroll
        for (int i = 0; i < ITEMS; i++)
            acc += valid[i] ? obj_of(X1[i], X2[i], Y1[i], Y2[i], Y3[i]) : 0.f;
        o[10] = acc;
    }

    // s_10 -> d_out optimistically (k_fix overwrites when K < 10)
#pragma unroll
    for (int i = 0; i < ITEMS; i++) {
        int b = base + i * NTH;
        if (valid[i]) {
            out[2 * b]     = X1[i];
            out[2 * b + 1] = X2[i];
            out[2 * B + 3 * b]     = Y1[i];
            out[2 * B + 3 * b + 1] = Y2[i];
            out[2 * B + 3 * b + 2] = Y3[i];
        }
    }

    // block reduction of objective partials -> g_part
    int lane = tid & 31;
    int wid  = tid >> 5;
    __shared__ float sm[(NTH / 32)][11];
#pragma unroll
    for (int t = 0; t < 11; t++) {
        float v = o[t];
#pragma unroll
        for (int off = 16; off > 0; off >>= 1)
            v += __shfl_down_sync(0xffffffffu, v, off);
        if (lane == 0) sm[wid][t] = v;
    }
    __syncthreads();
    if (wid == 0) {
#pragma unroll
        for (int t = 0; t < 11; t++) {
            float w = (lane < (NTH / 32)) ? sm[lane][t] : 0.f;
#pragma unroll
            for (int off = 4; off > 0; off >>= 1)
                w += __shfl_down_sync(0xffffffffu, w, off);
            if (lane == 0) g_part[t * MAXBLK + blockIdx.x] = (double)w;
        }
    }

    // arrival; only the last block stays to decide, everyone else exits now
    __threadfence();
    __shared__ int s_epoch, s_is_last;
    if (tid == 0) {
        int old = atomicAdd(&g_arrive, 1);
        s_epoch   = old / nblk;
        s_is_last = ((old % nblk) == (nblk - 1));
    }
    __syncthreads();
    if (!s_is_last) return;

    // ---- last block: reduce + accept-prefix scan, publish K ----
    __shared__ double red[NTH];
    __shared__ double osum[11];
    for (int t = 0; t < 11; t++) {
        double s = 0.0;
        for (int i = tid; i < nblk; i += NTH) s += g_part[t * MAXBLK + i];
        red[tid] = s;
        __syncthreads();
        for (int off = NTH / 2; off > 0; off >>= 1) {
            if (tid < off) red[tid] += red[tid + off];
            __syncthreads();
        }
        if (tid == 0) osum[t] = red[0];
        __syncthreads();
    }
    if (tid == 0) {
        double obj = osum[0];
        int K = 0;
        for (int t = 1; t <= 10; t++) {
            if (osum[t] < obj) { obj = osum[t]; K = t; }
            else break;   // a reject freezes the state forever (reg is a fp32 no-op)
        }
        atomicExch(&g_flag, (s_epoch + 1) * 16 + K);   // monotone publish
    }
}

// K2: recompute s_K when K < 10 (the real path for this dataset).
__global__ void __launch_bounds__(NTH, 4)
k_fix(const float* __restrict__ xin, const float* __restrict__ yin,
      float* __restrict__ out, int B) {
    int K = g_flag & 15;
    if (K == 10) return;
    int base = blockIdx.x * (NTH * ITEMS) + threadIdx.x;

    float X1[ITEMS], X2[ITEMS], Y1[ITEMS], Y2[ITEMS], Y3[ITEMS];
    bool  valid[ITEMS];
#pragma unroll
    for (int i = 0; i < ITEMS; i++) {
        int b = base + i * NTH;
        valid[i] = (b < B);
        if (valid[i]) {
            float2 xv = *reinterpret_cast<const float2*>(xin + 2 * b);
            X1[i] = xv.x; X2[i] = xv.y;
            Y1[i] = yin[3 * b]; Y2[i] = yin[3 * b + 1]; Y3[i] = yin[3 * b + 2];
        } else {
            X1[i] = 1.f; X2[i] = 0.f; Y1[i] = 1.f; Y2[i] = 0.f; Y3[i] = 0.f;
        }
    }
    for (int t = 0; t < K; t++) {
#pragma unroll
        for (int i = 0; i < ITEMS; i++)
            gn_step(X1[i], X2[i], Y1[i], Y2[i], Y3[i]);
    }
#pragma unroll
    for (int i = 0; i < ITEMS; i++) {
        int b = base + i * NTH;
        if (valid[i]) {
            out[2 * b]     = X1[i];
            out[2 * b + 1] = X2[i];
            out[2 * B + 3 * b]     = Y1[i];
            out[2 * B + 3 * b + 1] = Y2[i];
            out[2 * B + 3 * b + 2] = Y3[i];
        }
    }
}

extern "C" void kernel_launch(void* const* d_in, const int* in_sizes, int n_in,
                              void* d_out, int out_size) {
    const float* x = (const float*)d_in[0];   // (B,1,2) float32
    const float* y = (const float*)d_in[1];   // (B,3,1) float32
    int B = in_sizes[0] / 2;
    int nblk = (B + NTH * ITEMS - 1) / (NTH * ITEMS);   // 512 for B=262144

    k_main<<<nblk, NTH>>>(x, y, (float*)d_out, B, nblk);
    k_fix<<<nblk, NTH>>>(x, y, (float*)d_out, B);
}

// round 6
// speedup vs baseline: 1.1770x; 1.0368x over previous
#include <cuda_runtime.h>

#define NTH 256
#define MAXBLK 4096

typedef unsigned long long u64;

__device__ double g_part[11 * MAXBLK];
__device__ int    g_arrive;   // monotone across graph replays
__device__ int    g_flag;     // monotone: (epoch+1)*16 + K ; K = g_flag & 15

// ---------- packed f32x2 primitives (sm_100+) ----------
__device__ __forceinline__ u64 fma2(u64 a, u64 b, u64 c) {
    u64 d; asm("fma.rn.f32x2 %0, %1, %2, %3;" : "=l"(d) : "l"(a), "l"(b), "l"(c)); return d;
}
__device__ __forceinline__ u64 mul2(u64 a, u64 b) {
    u64 d; asm("mul.rn.f32x2 %0, %1, %2;" : "=l"(d) : "l"(a), "l"(b)); return d;
}
__device__ __forceinline__ u64 add2(u64 a, u64 b) {
    u64 d; asm("add.rn.f32x2 %0, %1, %2;" : "=l"(d) : "l"(a), "l"(b)); return d;
}
__device__ __forceinline__ u64 neg2(u64 a) { return a ^ 0x8000000080000000ull; }

__device__ __forceinline__ u64 pack2(float lo, float hi) {
    u64 d; asm("mov.b64 %0, {%1, %2};" : "=l"(d) : "f"(lo), "f"(hi)); return d;
}
__device__ __forceinline__ void unpack2(u64 a, float& lo, float& hi) {
    asm("mov.b64 {%0, %1}, %2;" : "=f"(lo), "=f"(hi) : "l"(a));
}
__device__ __forceinline__ float frcp(float a) {
    float r; asm("rcp.approx.f32 %0, %1;" : "=f"(r) : "f"(a)); return r;
}
__device__ __forceinline__ u64 rcp2(u64 a) {
    float lo, hi; unpack2(a, lo, hi);
    return pack2(frcp(lo), frcp(hi));
}

#define C3  0x4040000040400000ull   // {3.0f, 3.0f}
#define C2  0x4000000040000000ull   // {2.0f, 2.0f}

// Packed slim Gauss-Newton step (two independent problems per call).
// Returns packed objective at the INPUT state:
//   obj = 3Q + 2*(P1*S1 + S2) + Q*S2
__device__ __forceinline__ u64 gn2(u64& x1, u64& x2, u64& y1, u64& y2, u64& y3) {
    u64 S1 = add2(add2(y1, y2), y3);
    u64 S2 = fma2(y1, y1, fma2(y2, y2, mul2(y3, y3)));
    u64 Q  = fma2(x1, x1, mul2(x2, x2));
    u64 P1 = add2(x1, x2);
    u64 obj = fma2(Q, S2, fma2(C2, fma2(P1, S1, S2), mul2(C3, Q)));

    u64 A  = add2(S2, C3);
    u64 Bv = add2(Q, C2);
    u64 t  = rcp2(Bv);                  // Bv >= 2, safe

    u64 q1 = fma2(S1, x1, C3);
    u64 q2 = fma2(S1, x2, C3);
    u64 a1 = fma2(S2, x1, S1);
    u64 a2 = fma2(S2, x2, S1);

    u64 cc11 = fma2(a1, x1, q1);
    u64 cc12 = fma2(a1, x2, q1);
    u64 cc22 = fma2(a2, x2, q2);

    u64 tn  = neg2(t);
    u64 s11 = fma2(tn, cc11, A);
    u64 s12 = mul2(tn, cc12);
    u64 s22 = fma2(tn, cc22, A);

    u64 tP1n = mul2(tn, P1);
    u64 r1 = fma2(tP1n, q1, mul2(C3, x1));
    u64 r2 = fma2(tP1n, q2, mul2(C3, x2));

    u64 det  = fma2(s11, s22, neg2(mul2(s12, s12)));
    u64 invd = rcp2(det);

    u64 s12n = neg2(s12);
    u64 ux1 = mul2(fma2(s22, r1, mul2(s12n, r2)), invd);
    u64 ux2 = mul2(fma2(s11, r2, mul2(s12n, r1)), invd);

    u64 Su = add2(ux1, ux2);
    u64 xu = fma2(x1, ux1, mul2(x2, ux2));   // uses OLD x
    x1 = add2(x1, neg2(ux1));
    x2 = add2(x2, neg2(ux2));

    u64 c = add2(Su, neg2(P1));
    y1 = mul2(t, fma2(xu, y1, c));
    y2 = mul2(t, fma2(xu, y2, c));
    y3 = mul2(t, fma2(xu, y3, c));
    return obj;
}

__device__ __forceinline__ u64 obj2(u64 x1, u64 x2, u64 y1, u64 y2, u64 y3) {
    u64 S1 = add2(add2(y1, y2), y3);
    u64 S2 = fma2(y1, y1, fma2(y2, y2, mul2(y3, y3)));
    u64 Q  = fma2(x1, x1, mul2(x2, x2));
    u64 P1 = add2(x1, x2);
    return fma2(Q, S2, fma2(C2, fma2(P1, S1, S2), mul2(C3, Q)));
}

__device__ __forceinline__ void load_pair(const float* __restrict__ xin,
                                          const float* __restrict__ yin,
                                          int b0, int b1, int B,
                                          u64& x1, u64& x2, u64& y1, u64& y2, u64& y3,
                                          u64& mask) {
    bool v0 = (b0 < B), v1 = (b1 < B);
    float ax1 = 1.f, ax2 = 0.f, ay1 = 1.f, ay2 = 0.f, ay3 = 0.f;
    float bx1 = 1.f, bx2 = 0.f, by1 = 1.f, by2 = 0.f, by3 = 0.f;
    if (v0) {
        float2 xv = *reinterpret_cast<const float2*>(xin + 2 * b0);
        ax1 = xv.x; ax2 = xv.y;
        ay1 = yin[3 * b0]; ay2 = yin[3 * b0 + 1]; ay3 = yin[3 * b0 + 2];
    }
    if (v1) {
        float2 xv = *reinterpret_cast<const float2*>(xin + 2 * b1);
        bx1 = xv.x; bx2 = xv.y;
        by1 = yin[3 * b1]; by2 = yin[3 * b1 + 1]; by3 = yin[3 * b1 + 2];
    }
    x1 = pack2(ax1, bx1); x2 = pack2(ax2, bx2);
    y1 = pack2(ay1, by1); y2 = pack2(ay2, by2); y3 = pack2(ay3, by3);
    mask = (v0 ? 0x00000000FFFFFFFFull : 0ull) | (v1 ? 0xFFFFFFFF00000000ull : 0ull);
}

// K1: compute packed trajectories, emit block-partial objective sums, exit.
// Last-arriving block computes the accept-prefix K and publishes it.
__global__ void __launch_bounds__(NTH, 4)
k_main(const float* __restrict__ xin, const float* __restrict__ yin,
       int B, int nblk) {
    int tid  = threadIdx.x;
    int base = blockIdx.x * (NTH * 2) + tid;

    u64 x1, x2, y1, y2, y3, mask;
    load_pair(xin, yin, base, base + NTH, B, x1, x2, y1, y2, y3, mask);

    u64 o_pk[11];
#pragma unroll
    for (int t = 0; t < 10; t++)
        o_pk[t] = gn2(x1, x2, y1, y2, y3) & mask;
    o_pk[10] = obj2(x1, x2, y1, y2, y3) & mask;

    // block reduction of objective partials -> g_part
    int lane = tid & 31;
    int wid  = tid >> 5;
    __shared__ float sm[(NTH / 32)][11];
#pragma unroll
    for (int t = 0; t < 11; t++) {
        float lo, hi; unpack2(o_pk[t], lo, hi);
        float v = lo + hi;
#pragma unroll
        for (int off = 16; off > 0; off >>= 1)
            v += __shfl_down_sync(0xffffffffu, v, off);
        if (lane == 0) sm[wid][t] = v;
    }
    __syncthreads();
    if (wid == 0) {
#pragma unroll
        for (int t = 0; t < 11; t++) {
            float w = (lane < (NTH / 32)) ? sm[lane][t] : 0.f;
#pragma unroll
            for (int off = 4; off > 0; off >>= 1)
                w += __shfl_down_sync(0xffffffffu, w, off);
            if (lane == 0) g_part[t * MAXBLK + blockIdx.x] = (double)w;
        }
    }

    // arrival; only the last block stays to decide
    __threadfence();
    __shared__ int s_epoch, s_is_last;
    if (tid == 0) {
        int old = atomicAdd(&g_arrive, 1);
        s_epoch   = old / nblk;
        s_is_last = ((old % nblk) == (nblk - 1));
    }
    __syncthreads();
    if (!s_is_last) return;

    __shared__ double red[NTH];
    __shared__ double osum[11];
    for (int t = 0; t < 11; t++) {
        double s = 0.0;
        for (int i = tid; i < nblk; i += NTH) s += g_part[t * MAXBLK + i];
        red[tid] = s;
        __syncthreads();
        for (int off = NTH / 2; off > 0; off >>= 1) {
            if (tid < off) red[tid] += red[tid + off];
            __syncthreads();
        }
        if (tid == 0) osum[t] = red[0];
        __syncthreads();
    }
    if (tid == 0) {
        double obj = osum[0];
        int K = 0;
        for (int t = 1; t <= 10; t++) {
            if (osum[t] < obj) { obj = osum[t]; K = t; }
            else break;   // a reject freezes the state forever (reg is a fp32 no-op)
        }
        atomicExch(&g_flag, (s_epoch + 1) * 16 + K);   // monotone publish
    }
}

// K2: recompute s_K (any K, including 10) and write the output.
__global__ void __launch_bounds__(NTH, 4)
k_fix(const float* __restrict__ xin, const float* __restrict__ yin,
      float* __restrict__ out, int B) {
    int K = g_flag & 15;
    int base = blockIdx.x * (NTH * 2) + threadIdx.x;
    int b0 = base, b1 = base + NTH;

    u64 x1, x2, y1, y2, y3, mask;
    load_pair(xin, yin, b0, b1, B, x1, x2, y1, y2, y3, mask);

    for (int t = 0; t < K; t++)
        gn2(x1, x2, y1, y2, y3);

    float ax1, ax2, ay1, ay2, ay3, bx1, bx2, by1, by2, by3;
    unpack2(x1, ax1, bx1); unpack2(x2, ax2, bx2);
    unpack2(y1, ay1, by1); unpack2(y2, ay2, by2); unpack2(y3, ay3, by3);

    if (b0 < B) {
        out[2 * b0] = ax1; out[2 * b0 + 1] = ax2;
        out[2 * B + 3 * b0]     = ay1;
        out[2 * B + 3 * b0 + 1] = ay2;
        out[2 * B + 3 * b0 + 2] = ay3;
    }
    if (b1 < B) {
        out[2 * b1] = bx1; out[2 * b1 + 1] = bx2;
        out[2 * B + 3 * b1]     = by1;
        out[2 * B + 3 * b1 + 1] = by2;
        out[2 * B + 3 * b1 + 2] = by3;
    }
}

extern "C" void kernel_launch(void* const* d_in, const int* in_sizes, int n_in,
                              void* d_out, int out_size) {
    const float* x = (const float*)d_in[0];   // (B,1,2) float32
    const float* y = (const float*)d_in[1];   // (B,3,1) float32
    int B = in_sizes[0] / 2;
    int nblk = (B + NTH * 2 - 1) / (NTH * 2);   // 512 for B=262144

    k_main<<<nblk, NTH>>>(x, y, B, nblk);
    k_fix<<<nblk, NTH>>>(x, y, (float*)d_out, B);
}

// round 7
// speedup vs baseline: 1.3028x; 1.1069x over previous
#include <cuda_runtime.h>

#define NTH 256
#define MAXBLK 4096

typedef unsigned long long u64;

__device__ double g_part[11 * MAXBLK];
__device__ int    g_arrive;   // monotone across graph replays
__device__ int    g_flag;     // monotone: (epoch+1)*16 + K ; K = g_flag & 15

// ---------- packed f32x2 primitives (sm_100+) ----------
__device__ __forceinline__ u64 fma2(u64 a, u64 b, u64 c) {
    u64 d; asm("fma.rn.f32x2 %0, %1, %2, %3;" : "=l"(d) : "l"(a), "l"(b), "l"(c)); return d;
}
__device__ __forceinline__ u64 mul2(u64 a, u64 b) {
    u64 d; asm("mul.rn.f32x2 %0, %1, %2;" : "=l"(d) : "l"(a), "l"(b)); return d;
}
__device__ __forceinline__ u64 add2(u64 a, u64 b) {
    u64 d; asm("add.rn.f32x2 %0, %1, %2;" : "=l"(d) : "l"(a), "l"(b)); return d;
}
__device__ __forceinline__ u64 neg2(u64 a) { return a ^ 0x8000000080000000ull; }
__device__ __forceinline__ u64 sub2(u64 a, u64 b) { return add2(a, neg2(b)); }

__device__ __forceinline__ u64 pack2(float lo, float hi) {
    u64 d; asm("mov.b64 %0, {%1, %2};" : "=l"(d) : "f"(lo), "f"(hi)); return d;
}
__device__ __forceinline__ void unpack2(u64 a, float& lo, float& hi) {
    asm("mov.b64 {%0, %1}, %2;" : "=f"(lo), "=f"(hi) : "l"(a));
}
__device__ __forceinline__ float frcp(float a) {
    float r; asm("rcp.approx.f32 %0, %1;" : "=f"(r) : "f"(a)); return r;
}
__device__ __forceinline__ u64 rcp2(u64 a) {
    float lo, hi; unpack2(a, lo, hi);
    return pack2(frcp(lo), frcp(hi));
}

#define C3  0x4040000040400000ull   // {3.0f, 3.0f}
#define C2  0x4000000040000000ull   // {2.0f, 2.0f}

// y-free packed GN step on carried state (x1,x2,S1,S2) with affine y-tracking
// (al,be):  y' = txu*y + tc  =>  al' = txu*al, be' = txu*be + tc.
// Returns packed objective at the INPUT state: 3Q + 2(P1*S1 + S2) + Q*S2.
__device__ __forceinline__ u64 gn2(u64& x1, u64& x2, u64& S1, u64& S2,
                                   u64& al, u64& be) {
    u64 Q  = fma2(x1, x1, mul2(x2, x2));
    u64 P1 = add2(x1, x2);
    u64 obj = fma2(Q, S2, fma2(C2, fma2(P1, S1, S2), mul2(C3, Q)));

    u64 A  = add2(S2, C3);
    u64 Bv = add2(Q, C2);
    u64 t  = rcp2(Bv);                  // Bv >= 2, safe

    u64 q1 = fma2(S1, x1, C3);
    u64 q2 = fma2(S1, x2, C3);
    u64 a1 = fma2(S2, x1, S1);
    u64 a2 = fma2(S2, x2, S1);

    u64 cc11 = fma2(a1, x1, q1);
    u64 cc12 = fma2(a1, x2, q1);
    u64 cc22 = fma2(a2, x2, q2);

    u64 tn  = neg2(t);
    u64 s11 = fma2(tn, cc11, A);
    u64 s12 = mul2(tn, cc12);
    u64 s22 = fma2(tn, cc22, A);

    u64 tP1n = mul2(tn, P1);
    u64 r1 = fma2(tP1n, q1, mul2(C3, x1));
    u64 r2 = fma2(tP1n, q2, mul2(C3, x2));

    u64 det  = fma2(s11, s22, neg2(mul2(s12, s12)));
    u64 invd = rcp2(det);

    u64 s12n = neg2(s12);
    u64 ux1 = mul2(fma2(s22, r1, mul2(s12n, r2)), invd);
    u64 ux2 = mul2(fma2(s11, r2, mul2(s12n, r1)), invd);

    u64 Su = add2(ux1, ux2);
    u64 xu = fma2(x1, ux1, mul2(x2, ux2));   // uses OLD x
    x1 = sub2(x1, ux1);
    x2 = sub2(x2, ux2);

    u64 c   = sub2(Su, P1);
    u64 txu = mul2(t, xu);
    u64 tc  = mul2(t, c);

    al = mul2(txu, al);
    be = fma2(txu, be, tc);

    // S1' = txu*S1 + 3*tc ;  S2' = txu*(txu*S2 + 2*tc*S1) + 3*tc^2
    u64 S1n = fma2(txu, S1, mul2(C3, tc));
    u64 S2n = fma2(txu, fma2(txu, S2, mul2(mul2(C2, tc), S1)),
                   mul2(C3, mul2(tc, tc)));
    S1 = S1n; S2 = S2n;
    return obj;
}

__device__ __forceinline__ u64 obj_state(u64 x1, u64 x2, u64 S1, u64 S2) {
    u64 Q  = fma2(x1, x1, mul2(x2, x2));
    u64 P1 = add2(x1, x2);
    return fma2(Q, S2, fma2(C2, fma2(P1, S1, S2), mul2(C3, Q)));
}

// Load 2 problems into one packed chain; returns per-lane validity.
__device__ __forceinline__ void load_chain(const float* __restrict__ xin,
                                           const float* __restrict__ yin,
                                           int b0, int b1, int B,
                                           u64& x1, u64& x2, u64& S1, u64& S2,
                                           u64& y1, u64& y2, u64& y3,
                                           bool& v0, bool& v1) {
    v0 = (b0 < B); v1 = (b1 < B);
    float ax1 = 1.f, ax2 = 0.f, ay1 = 1.f, ay2 = 0.f, ay3 = 0.f;
    float bx1 = 1.f, bx2 = 0.f, by1 = 1.f, by2 = 0.f, by3 = 0.f;
    if (v0) {
        float2 xv = *reinterpret_cast<const float2*>(xin + 2 * b0);
        ax1 = xv.x; ax2 = xv.y;
        ay1 = yin[3 * b0]; ay2 = yin[3 * b0 + 1]; ay3 = yin[3 * b0 + 2];
    }
    if (v1) {
        float2 xv = *reinterpret_cast<const float2*>(xin + 2 * b1);
        bx1 = xv.x; bx2 = xv.y;
        by1 = yin[3 * b1]; by2 = yin[3 * b1 + 1]; by3 = yin[3 * b1 + 2];
    }
    x1 = pack2(ax1, bx1); x2 = pack2(ax2, bx2);
    y1 = pack2(ay1, by1); y2 = pack2(ay2, by2); y3 = pack2(ay3, by3);
    S1 = add2(add2(y1, y2), y3);
    S2 = fma2(y1, y1, fma2(y2, y2, mul2(y3, y3)));
}

__device__ __forceinline__ float masked_sum(u64 o, bool v0, bool v1) {
    float lo, hi; unpack2(o, lo, hi);
    return (v0 ? lo : 0.f) + (v1 ? hi : 0.f);
}

// K1: 4 problems/thread as 2 independent packed chains (ILP). No y in the
// loop. Emits block-partial objective sums; last block decides K. No spinning.
__global__ void __launch_bounds__(NTH, 2)
k_main(const float* __restrict__ xin, const float* __restrict__ yin,
       int B, int nblk) {
    int tid  = threadIdx.x;
    int base = blockIdx.x * (NTH * 4) + tid;

    u64 Ax1, Ax2, AS1, AS2, Aal = 0, Abe = 0, d1, d2, d3;
    u64 Bx1, Bx2, BS1, BS2, Bal = 0, Bbe = 0;
    bool va0, va1, vb0, vb1;
    load_chain(xin, yin, base,           base + NTH,     B, Ax1, Ax2, AS1, AS2, d1, d2, d3, va0, va1);
    load_chain(xin, yin, base + 2 * NTH, base + 3 * NTH, B, Bx1, Bx2, BS1, BS2, d1, d2, d3, vb0, vb1);

    float o[11];
#pragma unroll
    for (int t = 0; t < 10; t++) {
        u64 oa = gn2(Ax1, Ax2, AS1, AS2, Aal, Abe);
        u64 ob = gn2(Bx1, Bx2, BS1, BS2, Bal, Bbe);
        o[t] = masked_sum(oa, va0, va1) + masked_sum(ob, vb0, vb1);
    }
    o[10] = masked_sum(obj_state(Ax1, Ax2, AS1, AS2), va0, va1)
          + masked_sum(obj_state(Bx1, Bx2, BS1, BS2), vb0, vb1);

    // block reduction of objective partials -> g_part
    int lane = tid & 31;
    int wid  = tid >> 5;
    __shared__ float sm[(NTH / 32)][11];
#pragma unroll
    for (int t = 0; t < 11; t++) {
        float v = o[t];
#pragma unroll
        for (int off = 16; off > 0; off >>= 1)
            v += __shfl_down_sync(0xffffffffu, v, off);
        if (lane == 0) sm[wid][t] = v;
    }
    __syncthreads();
    if (wid == 0) {
#pragma unroll
        for (int t = 0; t < 11; t++) {
            float w = (lane < (NTH / 32)) ? sm[lane][t] : 0.f;
#pragma unroll
            for (int off = 4; off > 0; off >>= 1)
                w += __shfl_down_sync(0xffffffffu, w, off);
            if (lane == 0) g_part[t * MAXBLK + blockIdx.x] = (double)w;
        }
    }

    // arrival; only the last block stays to decide
    __threadfence();
    __shared__ int s_epoch, s_is_last;
    if (tid == 0) {
        int old = atomicAdd(&g_arrive, 1);
        s_epoch   = old / nblk;
        s_is_last = ((old % nblk) == (nblk - 1));
    }
    __syncthreads();
    if (!s_is_last) return;

    __shared__ double red[NTH];
    __shared__ double osum[11];
    for (int t = 0; t < 11; t++) {
        double s = 0.0;
        for (int i = tid; i < nblk; i += NTH) s += g_part[t * MAXBLK + i];
        red[tid] = s;
        __syncthreads();
        for (int off = NTH / 2; off > 0; off >>= 1) {
            if (tid < off) red[tid] += red[tid + off];
            __syncthreads();
        }
        if (tid == 0) osum[t] = red[0];
        __syncthreads();
    }
    if (tid == 0) {
        double obj = osum[0];
        int K = 0;
        for (int t = 1; t <= 10; t++) {
            if (osum[t] < obj) { obj = osum[t]; K = t; }
            else break;   // a reject freezes the state forever (reg is a fp32 no-op)
        }
        atomicExch(&g_flag, (s_epoch + 1) * 16 + K);   // monotone publish
    }
}

// K2: recompute s_K (any K) with the same y-free recurrence; reconstruct
// y_K = al*y0 + be at the end.
__global__ void __launch_bounds__(NTH, 2)
k_fix(const float* __restrict__ xin, const float* __restrict__ yin,
      float* __restrict__ out, int B) {
    int K = g_flag & 15;
    int tid  = threadIdx.x;
    int base = blockIdx.x * (NTH * 4) + tid;
    int b0 = base, b1 = base + NTH, b2 = base + 2 * NTH, b3 = base + 3 * NTH;

    u64 Ax1, Ax2, AS1, AS2, Ay1, Ay2, Ay3;
    u64 Bx1, Bx2, BS1, BS2, By1, By2, By3;
    u64 Aal = 0x3F8000003F800000ull, Abe = 0;   // {1.f,1.f}, {0,0}
    u64 Bal = 0x3F8000003F800000ull, Bbe = 0;
    bool va0, va1, vb0, vb1;
    load_chain(xin, yin, b0, b1, B, Ax1, Ax2, AS1, AS2, Ay1, Ay2, Ay3, va0, va1);
    load_chain(xin, yin, b2, b3, B, Bx1, Bx2, BS1, BS2, By1, By2, By3, vb0, vb1);

    for (int t = 0; t < K; t++) {
        gn2(Ax1, Ax2, AS1, AS2, Aal, Abe);
        gn2(Bx1, Bx2, BS1, BS2, Bal, Bbe);
    }

    // y_K = al * y0 + be
    Ay1 = fma2(Aal, Ay1, Abe); Ay2 = fma2(Aal, Ay2, Abe); Ay3 = fma2(Aal, Ay3, Abe);
    By1 = fma2(Bal, By1, Bbe); By2 = fma2(Bal, By2, Bbe); By3 = fma2(Bal, By3, Bbe);

    float lx1, lx2, ly1, ly2, ly3, hx1, hx2, hy1, hy2, hy3;

    unpack2(Ax1, lx1, hx1); unpack2(Ax2, lx2, hx2);
    unpack2(Ay1, ly1, hy1); unpack2(Ay2, ly2, hy2); unpack2(Ay3, ly3, hy3);
    if (va0) {
        out[2 * b0] = lx1; out[2 * b0 + 1] = lx2;
        out[2 * B + 3 * b0] = ly1; out[2 * B + 3 * b0 + 1] = ly2; out[2 * B + 3 * b0 + 2] = ly3;
    }
    if (va1) {
        out[2 * b1] = hx1; out[2 * b1 + 1] = hx2;
        out[2 * B + 3 * b1] = hy1; out[2 * B + 3 * b1 + 1] = hy2; out[2 * B + 3 * b1 + 2] = hy3;
    }

    unpack2(Bx1, lx1, hx1); unpack2(Bx2, lx2, hx2);
    unpack2(By1, ly1, hy1); unpack2(By2, ly2, hy2); unpack2(By3, ly3, hy3);
    if (vb0) {
        out[2 * b2] = lx1; out[2 * b2 + 1] = lx2;
        out[2 * B + 3 * b2] = ly1; out[2 * B + 3 * b2 + 1] = ly2; out[2 * B + 3 * b2 + 2] = ly3;
    }
    if (vb1) {
        out[2 * b3] = hx1; out[2 * b3 + 1] = hx2;
        out[2 * B + 3 * b3] = hy1; out[2 * B + 3 * b3 + 1] = hy2; out[2 * B + 3 * b3 + 2] = hy3;
    }
}

extern "C" void kernel_launch(void* const* d_in, const int* in_sizes, int n_in,
                              void* d_out, int out_size) {
    const float* x = (const float*)d_in[0];   // (B,1,2) float32
    const float* y = (const float*)d_in[1];   // (B,3,1) float32
    int B = in_sizes[0] / 2;
    int nblk = (B + NTH * 4 - 1) / (NTH * 4);   // 256 for B=262144

    k_main<<<nblk, NTH>>>(x, y, B, nblk);
    k_fix<<<nblk, NTH>>>(x, y, (float*)d_out, B);
}

// round 8
// speedup vs baseline: 1.3333x; 1.0234x over previous
#include <cuda_runtime.h>

#define NTH 256
#define MAXBLK 4096

typedef unsigned long long u64;

__device__ double g_part[11 * MAXBLK];
__device__ int    g_arrive;   // monotone across graph replays
__device__ int    g_flag;     // monotone: (epoch+1)*16 + K ; K = g_flag & 15

// ---------- packed f32x2 primitives (sm_100+) ----------
__device__ __forceinline__ u64 fma2(u64 a, u64 b, u64 c) {
    u64 d; asm("fma.rn.f32x2 %0, %1, %2, %3;" : "=l"(d) : "l"(a), "l"(b), "l"(c)); return d;
}
__device__ __forceinline__ u64 mul2(u64 a, u64 b) {
    u64 d; asm("mul.rn.f32x2 %0, %1, %2;" : "=l"(d) : "l"(a), "l"(b)); return d;
}
__device__ __forceinline__ u64 add2(u64 a, u64 b) {
    u64 d; asm("add.rn.f32x2 %0, %1, %2;" : "=l"(d) : "l"(a), "l"(b)); return d;
}
__device__ __forceinline__ u64 neg2(u64 a) { return a ^ 0x8000000080000000ull; }
__device__ __forceinline__ u64 sub2(u64 a, u64 b) { return add2(a, neg2(b)); }

__device__ __forceinline__ u64 pack2(float lo, float hi) {
    u64 d; asm("mov.b64 %0, {%1, %2};" : "=l"(d) : "f"(lo), "f"(hi)); return d;
}
__device__ __forceinline__ void unpack2(u64 a, float& lo, float& hi) {
    asm("mov.b64 {%0, %1}, %2;" : "=f"(lo), "=f"(hi) : "l"(a));
}
__device__ __forceinline__ float frcp(float a) {
    float r; asm("rcp.approx.f32 %0, %1;" : "=f"(r) : "f"(a)); return r;
}
__device__ __forceinline__ u64 rcp2(u64 a) {
    float lo, hi; unpack2(a, lo, hi);
    return pack2(frcp(lo), frcp(hi));
}

#define C3   0x4040000040400000ull   // {3.0f, 3.0f}
#define C2   0x4000000040000000ull   // {2.0f, 2.0f}
#define ONE2 0x3F8000003F800000ull   // {1.0f, 1.0f}

// y-free packed GN step with SINGLE rcp on the critical path:
//   M  = A*Bv*I - CC^T  (Bv-scaled Schur complement, exact algebra)
//   r~ = 3*Bv*x - P1*q ;  u = M^{-1} r~
// t = 1/Bv feeds only the y/S affine recurrences (off the u-chain).
// Returns packed objective at the INPUT state: 3Q + 2(P1*S1 + S2) + Q*S2.
__device__ __forceinline__ u64 gn2(u64& x1, u64& x2, u64& S1, u64& S2,
                                   u64& al, u64& be) {
    u64 Q  = fma2(x1, x1, mul2(x2, x2));
    u64 P1 = add2(x1, x2);
    u64 obj = fma2(Q, S2, fma2(C2, fma2(P1, S1, S2), mul2(C3, Q)));

    u64 A  = add2(S2, C3);
    u64 Bv = add2(Q, C2);
    u64 t  = rcp2(Bv);                  // parallel to the M/det chain

    u64 q1 = fma2(S1, x1, C3);
    u64 q2 = fma2(S1, x2, C3);
    u64 a1 = fma2(S2, x1, S1);
    u64 a2 = fma2(S2, x2, S1);

    u64 cc11 = fma2(a1, x1, q1);
    u64 cc12 = fma2(a1, x2, q1);
    u64 cc22 = fma2(a2, x2, q2);

    u64 AB  = mul2(A, Bv);
    u64 m11 = sub2(AB, cc11);
    u64 m22 = sub2(AB, cc22);

    u64 B3 = mul2(C3, Bv);
    u64 r1 = fma2(B3, x1, neg2(mul2(P1, q1)));
    u64 r2 = fma2(B3, x2, neg2(mul2(P1, q2)));

    u64 detM = fma2(m11, m22, neg2(mul2(cc12, cc12)));
    u64 i    = rcp2(detM);              // the ONE rcp on the critical path

    // M = [[m11,-cc12],[-cc12,m22]] -> adj = [[m22, cc12],[cc12, m11]]
    u64 ux1 = mul2(fma2(m22, r1, mul2(cc12, r2)), i);
    u64 ux2 = mul2(fma2(m11, r2, mul2(cc12, r1)), i);

    u64 Su = add2(ux1, ux2);
    u64 xu = fma2(x1, ux1, mul2(x2, ux2));   // uses OLD x
    x1 = sub2(x1, ux1);
    x2 = sub2(x2, ux2);

    u64 c   = sub2(Su, P1);
    u64 txu = mul2(t, xu);
    u64 tc  = mul2(t, c);

    al = mul2(txu, al);
    be = fma2(txu, be, tc);

    u64 S1n = fma2(txu, S1, mul2(C3, tc));
    u64 S2n = fma2(txu, fma2(txu, S2, mul2(mul2(C2, tc), S1)),
                   mul2(C3, mul2(tc, tc)));
    S1 = S1n; S2 = S2n;
    return obj;
}

__device__ __forceinline__ u64 obj_state(u64 x1, u64 x2, u64 S1, u64 S2) {
    u64 Q  = fma2(x1, x1, mul2(x2, x2));
    u64 P1 = add2(x1, x2);
    return fma2(Q, S2, fma2(C2, fma2(P1, S1, S2), mul2(C3, Q)));
}

__device__ __forceinline__ void load_chain(const float* __restrict__ xin,
                                           const float* __restrict__ yin,
                                           int b0, int b1, int B,
                                           u64& x1, u64& x2, u64& S1, u64& S2,
                                           u64& y1, u64& y2, u64& y3,
                                           bool& v0, bool& v1) {
    v0 = (b0 < B); v1 = (b1 < B);
    float ax1 = 1.f, ax2 = 0.f, ay1 = 1.f, ay2 = 0.f, ay3 = 0.f;
    float bx1 = 1.f, bx2 = 0.f, by1 = 1.f, by2 = 0.f, by3 = 0.f;
    if (v0) {
        float2 xv = *reinterpret_cast<const float2*>(xin + 2 * b0);
        ax1 = xv.x; ax2 = xv.y;
        ay1 = yin[3 * b0]; ay2 = yin[3 * b0 + 1]; ay3 = yin[3 * b0 + 2];
    }
    if (v1) {
        float2 xv = *reinterpret_cast<const float2*>(xin + 2 * b1);
        bx1 = xv.x; bx2 = xv.y;
        by1 = yin[3 * b1]; by2 = yin[3 * b1 + 1]; by3 = yin[3 * b1 + 2];
    }
    x1 = pack2(ax1, bx1); x2 = pack2(ax2, bx2);
    y1 = pack2(ay1, by1); y2 = pack2(ay2, by2); y3 = pack2(ay3, by3);
    S1 = add2(add2(y1, y2), y3);
    S2 = fma2(y1, y1, fma2(y2, y2, mul2(y3, y3)));
}

__device__ __forceinline__ float masked_sum(u64 o, bool v0, bool v1) {
    float lo, hi; unpack2(o, lo, hi);
    return (v0 ? lo : 0.f) + (v1 ? hi : 0.f);
}

__device__ __forceinline__ void store_chain(float* __restrict__ out, int B,
                                            int b0, int b1, bool v0, bool v1,
                                            u64 x1, u64 x2, u64 y1, u64 y2, u64 y3) {
    float lx1, lx2, ly1, ly2, ly3, hx1, hx2, hy1, hy2, hy3;
    unpack2(x1, lx1, hx1); unpack2(x2, lx2, hx2);
    unpack2(y1, ly1, hy1); unpack2(y2, ly2, hy2); unpack2(y3, ly3, hy3);
    if (v0) {
        out[2 * b0] = lx1; out[2 * b0 + 1] = lx2;
        out[2 * B + 3 * b0] = ly1; out[2 * B + 3 * b0 + 1] = ly2; out[2 * B + 3 * b0 + 2] = ly3;
    }
    if (v1) {
        out[2 * b1] = hx1; out[2 * b1 + 1] = hx2;
        out[2 * B + 3 * b1] = hy1; out[2 * B + 3 * b1 + 1] = hy2; out[2 * B + 3 * b1 + 2] = hy3;
    }
}

// Fused kernel. All 256 blocks resident (launch_bounds(256,2) -> <=128 regs ->
// 296 capacity), so the flag-poll cannot deadlock.
__global__ void __launch_bounds__(NTH, 2)
k_all(const float* __restrict__ xin, const float* __restrict__ yin,
      float* __restrict__ out, int B, int nblk) {
    int tid  = threadIdx.x;
    int base = blockIdx.x * (NTH * 4) + tid;
    int b0 = base, b1 = base + NTH, b2 = base + 2 * NTH, b3 = base + 3 * NTH;

    // ---- phase 1: 10 GN steps, 2 independent packed chains ----
    u64 Ax1, Ax2, AS1, AS2, Aal = ONE2, Abe = 0, d1, d2, d3;
    u64 Bx1, Bx2, BS1, BS2, Bal = ONE2, Bbe = 0;
    bool va0, va1, vb0, vb1;
    load_chain(xin, yin, b0, b1, B, Ax1, Ax2, AS1, AS2, d1, d2, d3, va0, va1);
    load_chain(xin, yin, b2, b3, B, Bx1, Bx2, BS1, BS2, d1, d2, d3, vb0, vb1);

    float o[11];
#pragma unroll
    for (int t = 0; t < 10; t++) {
        u64 oa = gn2(Ax1, Ax2, AS1, AS2, Aal, Abe);
        u64 ob = gn2(Bx1, Bx2, BS1, BS2, Bal, Bbe);
        o[t] = masked_sum(oa, va0, va1) + masked_sum(ob, vb0, vb1);
    }
    o[10] = masked_sum(obj_state(Ax1, Ax2, AS1, AS2), va0, va1)
          + masked_sum(obj_state(Bx1, Bx2, BS1, BS2), vb0, vb1);

    // block reduction of objective partials -> g_part
    int lane = tid & 31;
    int wid  = tid >> 5;
    __shared__ float sm[(NTH / 32)][11];
#pragma unroll
    for (int t = 0; t < 11; t++) {
        float v = o[t];
#pragma unroll
        for (int off = 16; off > 0; off >>= 1)
            v += __shfl_down_sync(0xffffffffu, v, off);
        if (lane == 0) sm[wid][t] = v;
    }
    __syncthreads();
    if (wid == 0) {
#pragma unroll
        for (int t = 0; t < 11; t++) {
            float w = (lane < (NTH / 32)) ? sm[lane][t] : 0.f;
#pragma unroll
            for (int off = 4; off > 0; off >>= 1)
                w += __shfl_down_sync(0xffffffffu, w, off);
            if (lane == 0) g_part[t * MAXBLK + blockIdx.x] = (double)w;
        }
    }

    // ---- arrival; last block decides K ----
    __threadfence();
    __shared__ int s_epoch, s_is_last, s_K;
    if (tid == 0) {
        int old = atomicAdd(&g_arrive, 1);
        s_epoch   = old / nblk;
        s_is_last = ((old % nblk) == (nblk - 1));
    }
    __syncthreads();
    int epoch = s_epoch;

    if (s_is_last) {
        __shared__ double red[NTH];
        __shared__ double osum[11];
        for (int t = 0; t < 11; t++) {
            double s = 0.0;
            for (int i = tid; i < nblk; i += NTH) s += g_part[t * MAXBLK + i];
            red[tid] = s;
            __syncthreads();
            for (int off = NTH / 2; off > 0; off >>= 1) {
                if (tid < off) red[tid] += red[tid + off];
                __syncthreads();
            }
            if (tid == 0) osum[t] = red[0];
            __syncthreads();
        }
        if (tid == 0) {
            double obj = osum[0];
            int K = 0;
            for (int t = 1; t <= 10; t++) {
                if (osum[t] < obj) { obj = osum[t]; K = t; }
                else break;   // reject freezes the state (reg is a fp32 no-op)
            }
            atomicExch(&g_flag, (epoch + 1) * 16 + K);   // monotone publish
        }
    }

    // ---- poll for the decision (read-only, nanosleep backoff) ----
    int target = (epoch + 1) * 16;
    if (tid == 0) {
        int f = *(volatile int*)&g_flag;
        while (f < target) { __nanosleep(100); f = *(volatile int*)&g_flag; }
        s_K = f - target;
    }
    __syncthreads();
    int K = s_K;

    // ---- phase 2: materialize s_K ----
    if (K == 10) {
        // phase-1 end state is s_10; just reconstruct y = al*y0 + be
        u64 w1, w2, ws1, ws2, Ay1, Ay2, Ay3, By1, By2, By3;
        bool t0, t1;
        load_chain(xin, yin, b0, b1, B, w1, w2, ws1, ws2, Ay1, Ay2, Ay3, t0, t1);
        load_chain(xin, yin, b2, b3, B, w1, w2, ws1, ws2, By1, By2, By3, t0, t1);
        Ay1 = fma2(Aal, Ay1, Abe); Ay2 = fma2(Aal, Ay2, Abe); Ay3 = fma2(Aal, Ay3, Abe);
        By1 = fma2(Bal, By1, Bbe); By2 = fma2(Bal, By2, Bbe); By3 = fma2(Bal, By3, Bbe);
        store_chain(out, B, b0, b1, va0, va1, Ax1, Ax2, Ay1, Ay2, Ay3);
        store_chain(out, B, b2, b3, vb0, vb1, Bx1, Bx2, By1, By2, By3);
    } else {
        u64 Ay1, Ay2, Ay3, By1, By2, By3;
        Aal = ONE2; Abe = 0; Bal = ONE2; Bbe = 0;
        load_chain(xin, yin, b0, b1, B, Ax1, Ax2, AS1, AS2, Ay1, Ay2, Ay3, va0, va1);
        load_chain(xin, yin, b2, b3, B, Bx1, Bx2, BS1, BS2, By1, By2, By3, vb0, vb1);
        for (int t = 0; t < K; t++) {
            gn2(Ax1, Ax2, AS1, AS2, Aal, Abe);
            gn2(Bx1, Bx2, BS1, BS2, Bal, Bbe);
        }
        Ay1 = fma2(Aal, Ay1, Abe); Ay2 = fma2(Aal, Ay2, Abe); Ay3 = fma2(Aal, Ay3, Abe);
        By1 = fma2(Bal, By1, Bbe); By2 = fma2(Bal, By2, Bbe); By3 = fma2(Bal, By3, Bbe);
        store_chain(out, B, b0, b1, va0, va1, Ax1, Ax2, Ay1, Ay2, Ay3);
        store_chain(out, B, b2, b3, vb0, vb1, Bx1, Bx2, By1, By2, By3);
    }
}

extern "C" void kernel_launch(void* const* d_in, const int* in_sizes, int n_in,
                              void* d_out, int out_size) {
    const float* x = (const float*)d_in[0];   // (B,1,2) float32
    const float* y = (const float*)d_in[1];   // (B,3,1) float32
    int B = in_sizes[0] / 2;
    int nblk = (B + NTH * 4 - 1) / (NTH * 4);   // 256 for B=262144

    k_all<<<nblk, NTH>>>(x, y, (float*)d_out, B, nblk);
}